// round 15
// baseline (speedup 1.0000x reference)
#include <cuda_runtime.h>
#include <cuda_fp16.h>
#include <math.h>
#include <stdint.h>

#define BB 4
#define ND 512
#define NT 512
#define DM 256
#define NH 8
#define DK 32

// ---- scratch (static device globals; no runtime allocation) ----
__device__ __half g_deth[BB*ND*DM];       // detections fp16
__device__ __half g_trkh[BB*NT*DM];       // tracks fp16
__device__ __half g_wqh[DM*DM], g_wkh[DM*DM], g_wvh[DM*DM], g_woh[DM*DM];
__device__ __half g_w1h[128*DM];
__device__ __half g_Qh[BB*NH*ND*DK];      // [bh][q][dk]
__device__ __half g_Kh[BB*NH*NT*DK];      // [bh][t][dk]
__device__ __half g_Vht[BB*NH*DK*NT];     // [bh][dk][t]  (transposed)
__device__ __half g_ctxh[BB*ND*DM];       // attention output fp16 [token][256]
__device__ float g_x[BB*ND*DM];           // residual x = det + attended (fp32)

static __device__ __forceinline__ uint32_t sm_u32(const void* p) {
    uint32_t a;
    asm("{ .reg .u64 t; cvta.to.shared.u64 t, %1; cvt.u32.u64 %0, t; }"
        : "=r"(a) : "l"(p));
    return a;
}
static __device__ __forceinline__ uint32_t f2h2(float a, float b) {
    __half2 h = __floats2half2_rn(a, b);
    return *reinterpret_cast<uint32_t*>(&h);
}

#define LDSM_X4(r, addr) \
    asm volatile("ldmatrix.sync.aligned.m8n8.x4.shared.b16 {%0,%1,%2,%3}, [%4];" \
        : "=r"((r)[0]), "=r"((r)[1]), "=r"((r)[2]), "=r"((r)[3]) : "r"(addr))
#define MMA16816(c, a, b0, b1) \
    asm volatile("mma.sync.aligned.m16n8k16.row.col.f32.f16.f16.f32 " \
        "{%0,%1,%2,%3}, {%4,%5,%6,%7}, {%8,%9}, {%0,%1,%2,%3};" \
        : "+f"((c)[0]), "+f"((c)[1]), "+f"((c)[2]), "+f"((c)[3]) \
        : "r"((a)[0]), "r"((a)[1]), "r"((a)[2]), "r"((a)[3]), "r"(b0), "r"(b1))

// ============================================================
// prep: fp32 -> fp16 copies (everything converted exactly once)
// ============================================================
__global__ void prep_half(const float* __restrict__ det,
                          const float* __restrict__ trk,
                          const float* __restrict__ w_q, const float* __restrict__ w_k,
                          const float* __restrict__ w_v, const float* __restrict__ w_o,
                          const float* __restrict__ w1)
{
    int idx = blockIdx.x * 256 + threadIdx.x;   // 0 .. 524287
    g_deth[idx] = __float2half_rn(det[idx]);
    g_trkh[idx] = __float2half_rn(trk[idx]);
    if (idx < DM * DM) {
        g_wqh[idx] = __float2half_rn(w_q[idx]);
        g_wkh[idx] = __float2half_rn(w_k[idx]);
        g_wvh[idx] = __float2half_rn(w_v[idx]);
        g_woh[idx] = __float2half_rn(w_o[idx]);
    }
    if (idx < 128 * DM) g_w1h[idx] = __float2half_rn(w1[idx]);
}

// ============================================================
// Projection GEMM (fp16 mma, pre-converted inputs):
//   z = 0: Q -> g_Qh;  z = 1: K -> g_Kh;  z = 2: V -> g_Vht via smem transpose
// ============================================================
#define PALD 264
#define TLD 72
#define PROJ_SMEM ((64 * PALD + 128 * PALD) * 2)   // 101376

__global__ void __launch_bounds__(256)
proj_gemm(const float* __restrict__ b_q, const float* __restrict__ b_k,
          const float* __restrict__ b_v)
{
    int z = blockIdx.z;
    const __half* X = (z == 0) ? g_deth : g_trkh;
    const __half* W = (z == 0) ? g_wqh : (z == 1) ? g_wkh : g_wvh;
    const float* bias = (z == 0) ? b_q : (z == 1) ? b_k : b_v;

    extern __shared__ __align__(16) char dyn[];
    __half* As = (__half*)dyn;                      // [64][PALD]
    __half* Bs = (__half*)(dyn + 64 * PALD * 2);    // [128][PALD]
    __half* T  = (__half*)dyn;                      // overlay: [128 col][TLD]

    int tid = threadIdx.x;
    int warp = tid >> 5, lane = tid & 31;
    int m0 = blockIdx.x * 64, n0blk = blockIdx.y * 128;
    int wm = (warp & 3) * 16, wn = (warp >> 2) * 64;
    int tg = lane & 3, g = lane >> 2;

    #pragma unroll
    for (int i = 0; i < 8; i++) {
        int idx = tid + i * 256;
        int row = idx >> 5, kg = idx & 31;
        *(uint4*)(As + row * PALD + kg * 8) =
            *(const uint4*)(X + (size_t)(m0 + row) * 256 + kg * 8);
    }
    #pragma unroll
    for (int i = 0; i < 16; i++) {
        int idx = tid + i * 256;
        int row = idx >> 5, kg = idx & 31;
        *(uint4*)(Bs + row * PALD + kg * 8) =
            *(const uint4*)(W + (size_t)(n0blk + row) * 256 + kg * 8);
    }
    __syncthreads();

    uint32_t a_base = sm_u32(As) + (((wm + (lane & 15)) * PALD + (lane >> 4) * 8) << 1);
    uint32_t b_base = sm_u32(Bs) +
        (((wn + ((lane >> 4) << 3) + (lane & 7)) * PALD + ((lane >> 3) & 1) * 8) << 1);

    float c[8][4];
    #pragma unroll
    for (int nj = 0; nj < 8; nj++)
        #pragma unroll
        for (int k = 0; k < 4; k++) c[nj][k] = 0.f;

    #pragma unroll
    for (int kt = 0; kt < 16; kt++) {
        uint32_t a[4];
        LDSM_X4(a, a_base + kt * 32);
        uint32_t bb[4][4];
        #pragma unroll
        for (int p = 0; p < 4; p++)
            LDSM_X4(bb[p], b_base + p * 16 * PALD * 2 + kt * 32);
        #pragma unroll
        for (int nj = 0; nj < 8; nj++)
            MMA16816(c[nj], a, bb[nj >> 1][(nj & 1) * 2], bb[nj >> 1][(nj & 1) * 2 + 1]);
    }

    if (z != 2) {
        #pragma unroll
        for (int r = 0; r < 2; r++) {
            int token = m0 + wm + g + r * 8;
            int b = token >> 9, tk = token & 511;
            #pragma unroll
            for (int nj = 0; nj < 8; nj++) {
                int col = n0blk + wn + nj * 8 + tg * 2;
                int h = col >> 5, dk = col & 31;
                float v0 = c[nj][r * 2 + 0] + bias[col];
                float v1 = c[nj][r * 2 + 1] + bias[col + 1];
                int bh = b * NH + h;
                if (z == 0) {
                    *(__half2*)&g_Qh[((size_t)(bh * ND + tk)) * DK + dk] =
                        __floats2half2_rn(v0, v1);
                } else {
                    *(__half2*)&g_Kh[((size_t)(bh * NT + tk)) * DK + dk] =
                        __floats2half2_rn(v0, v1);
                }
            }
        }
    } else {
        __syncthreads();
        #pragma unroll
        for (int r = 0; r < 2; r++) {
            int tok = wm + g + r * 8;
            #pragma unroll
            for (int nj = 0; nj < 8; nj++) {
                int col = wn + nj * 8 + tg * 2;
                T[col * TLD + tok]       =
                    __float2half_rn(c[nj][r * 2 + 0] + b_v[n0blk + col]);
                T[(col + 1) * TLD + tok] =
                    __float2half_rn(c[nj][r * 2 + 1] + b_v[n0blk + col + 1]);
            }
        }
        __syncthreads();
        int b = m0 >> 9, tk0 = m0 & 511;
        #pragma unroll
        for (int i = 0; i < 4; i++) {
            int idx = tid + i * 256;
            int cloc = idx >> 3, part = idx & 7;
            int gcol = n0blk + cloc;
            int h = gcol >> 5, dk = gcol & 31;
            *(uint4*)&g_Vht[((size_t)((b * NH + h) * DK + dk)) * NT + tk0 + part * 8] =
                *(const uint4*)(T + cloc * TLD + part * 8);
        }
    }
}

// ============================================================
// Flash attention v4 (round-14 version): double-buffered K/V,
// register prefetch, ONE barrier per chunk, no-max softmax.
// ============================================================
#define QLD 40
#define VLD 72
#define KBUF (64 * QLD)
#define VBUF (32 * VLD)

__global__ void __launch_bounds__(128) attn_tc()
{
    __shared__ __half Qs[64 * QLD];
    __shared__ __half Ks[2][KBUF];
    __shared__ __half Vt[2][VBUF];

    int bh = blockIdx.z * NH + blockIdx.y;
    int q0 = blockIdx.x * 64;
    int h  = blockIdx.y;
    int tid = threadIdx.x;
    int warp = tid >> 5, lane = tid & 31;
    int tg = lane & 3, g = lane >> 2;

    int krow0 = tid >> 2,         kpart0 = tid & 3;
    int krow1 = (tid + 128) >> 2, kpart1 = tid & 3;
    int vrow0 = tid >> 3,         vpart0 = tid & 7;
    int vrow1 = (tid + 128) >> 3, vpart1 = tid & 7;

    #pragma unroll
    for (int i = 0; i < 2; i++) {
        int idx = tid + i * 128;
        int row = idx >> 2, part = idx & 3;
        *(uint4*)(Qs + row * QLD + part * 8) =
            *(const uint4*)(g_Qh + ((size_t)(bh * ND + q0 + row)) * DK + part * 8);
    }
    *(uint4*)(Ks[0] + krow0 * QLD + kpart0 * 8) =
        *(const uint4*)(g_Kh + ((size_t)(bh * NT + krow0)) * DK + kpart0 * 8);
    *(uint4*)(Ks[0] + krow1 * QLD + kpart1 * 8) =
        *(const uint4*)(g_Kh + ((size_t)(bh * NT + krow1)) * DK + kpart1 * 8);
    *(uint4*)(Vt[0] + vrow0 * VLD + vpart0 * 8) =
        *(const uint4*)(g_Vht + ((size_t)(bh * DK + vrow0)) * NT + vpart0 * 8);
    *(uint4*)(Vt[0] + vrow1 * VLD + vpart1 * 8) =
        *(const uint4*)(g_Vht + ((size_t)(bh * DK + vrow1)) * NT + vpart1 * 8);
    __syncthreads();

    uint32_t aq_base = sm_u32(Qs) +
        (((warp * 16 + (lane & 15)) * QLD + (lane >> 4) * 8) << 1);
    uint32_t bk0 = sm_u32(Ks) +
        (((((lane >> 4) << 3) + (lane & 7)) * QLD + ((lane >> 3) & 1) * 8) << 1);
    uint32_t bv0 = sm_u32(Vt) +
        (((((lane >> 4) << 3) + (lane & 7)) * VLD + ((lane >> 3) & 1) * 8) << 1);

    uint32_t aQ[2][4];
    LDSM_X4(aQ[0], aq_base);
    LDSM_X4(aQ[1], aq_base + 32);

    const float scale = 0.17677669529663689f;
    float l0 = 0.f, l1 = 0.f;
    float c2[4][4];
    #pragma unroll
    for (int nt = 0; nt < 4; nt++)
        #pragma unroll
        for (int k = 0; k < 4; k++) c2[nt][k] = 0.f;

    for (int ch = 0; ch < 8; ch++) {
        uint4 kpre0, kpre1, vpre0, vpre1;
        if (ch < 7) {
            int t0 = (ch + 1) * 64;
            kpre0 = *(const uint4*)(g_Kh + ((size_t)(bh * NT + t0 + krow0)) * DK + kpart0 * 8);
            kpre1 = *(const uint4*)(g_Kh + ((size_t)(bh * NT + t0 + krow1)) * DK + kpart1 * 8);
            vpre0 = *(const uint4*)(g_Vht + ((size_t)(bh * DK + vrow0)) * NT + t0 + vpart0 * 8);
            vpre1 = *(const uint4*)(g_Vht + ((size_t)(bh * DK + vrow1)) * NT + t0 + vpart1 * 8);
        }

        int cur = ch & 1;
        uint32_t bk_base = bk0 + cur * (KBUF * 2);
        uint32_t bv_base = bv0 + cur * (VBUF * 2);

        float c[8][4];
        #pragma unroll
        for (int nj = 0; nj < 8; nj++)
            #pragma unroll
            for (int k = 0; k < 4; k++) c[nj][k] = 0.f;
        #pragma unroll
        for (int kt = 0; kt < 2; kt++) {
            uint32_t bb[4][4];
            #pragma unroll
            for (int p = 0; p < 4; p++)
                LDSM_X4(bb[p], bk_base + p * 16 * QLD * 2 + kt * 32);
            #pragma unroll
            for (int nj = 0; nj < 8; nj++)
                MMA16816(c[nj], aQ[kt],
                         bb[nj >> 1][(nj & 1) * 2], bb[nj >> 1][(nj & 1) * 2 + 1]);
        }

        uint32_t af[4][4];
        #pragma unroll
        for (int nj = 0; nj < 8; nj++) {
            float p0 = __expf(fminf(c[nj][0] * scale, 11.f));
            float p1 = __expf(fminf(c[nj][1] * scale, 11.f));
            float p2 = __expf(fminf(c[nj][2] * scale, 11.f));
            float p3 = __expf(fminf(c[nj][3] * scale, 11.f));
            l0 += p0 + p1; l1 += p2 + p3;
            int kt = nj >> 1, half = (nj & 1) * 2;
            af[kt][half]     = f2h2(p0, p1);
            af[kt][half + 1] = f2h2(p2, p3);
        }

        #pragma unroll
        for (int kt = 0; kt < 4; kt++) {
            uint32_t bb[2][4];
            #pragma unroll
            for (int p = 0; p < 2; p++)
                LDSM_X4(bb[p], bv_base + p * 16 * VLD * 2 + kt * 32);
            #pragma unroll
            for (int nt = 0; nt < 4; nt++)
                MMA16816(c2[nt], af[kt],
                         bb[nt >> 1][(nt & 1) * 2], bb[nt >> 1][(nt & 1) * 2 + 1]);
        }

        if (ch < 7) {
            int nxt = cur ^ 1;
            *(uint4*)(Ks[nxt] + krow0 * QLD + kpart0 * 8) = kpre0;
            *(uint4*)(Ks[nxt] + krow1 * QLD + kpart1 * 8) = kpre1;
            *(uint4*)(Vt[nxt] + vrow0 * VLD + vpart0 * 8) = vpre0;
            *(uint4*)(Vt[nxt] + vrow1 * VLD + vpart1 * 8) = vpre1;
            __syncthreads();
        }
    }

    l0 += __shfl_xor_sync(0xffffffffu, l0, 1);
    l0 += __shfl_xor_sync(0xffffffffu, l0, 2);
    l1 += __shfl_xor_sync(0xffffffffu, l1, 1);
    l1 += __shfl_xor_sync(0xffffffffu, l1, 2);

    float inv0 = 1.f / l0, inv1 = 1.f / l1;
    int token = q0 + warp * 16 + g;
    #pragma unroll
    for (int nt = 0; nt < 4; nt++) {
        int col = h * DK + nt * 8 + tg * 2;
        size_t base_b = (size_t)(blockIdx.z * ND);
        *(__half2*)&g_ctxh[(base_b + token) * DM + col] =
            __floats2half2_rn(c2[nt][0] * inv0, c2[nt][1] * inv0);
        *(__half2*)&g_ctxh[(base_b + token + 8) * DM + col] =
            __floats2half2_rn(c2[nt][2] * inv1, c2[nt][3] * inv1);
    }
}

// ============================================================
// output projection + residual (64x64 tiles, 128 blocks):
//   x = ctxh @ w_o^T + b_o + det  (fp32)
// ============================================================
#define GO_SMEM ((64 * PALD + 64 * PALD) * 2)   // 67584

__global__ void __launch_bounds__(256)
gemm_o_tc(const float* __restrict__ b_o, const float* __restrict__ det)
{
    extern __shared__ __align__(16) char dyn[];
    __half* As = (__half*)dyn;                   // [64][PALD]
    __half* Bs = (__half*)(dyn + 64 * PALD * 2); // [64][PALD]

    int tid = threadIdx.x;
    int warp = tid >> 5, lane = tid & 31;
    int m0 = blockIdx.x * 64, n0blk = blockIdx.y * 64;
    int wm = (warp & 3) * 16, wn = (warp >> 2) * 32;
    int tg = lane & 3, g = lane >> 2;

    #pragma unroll
    for (int i = 0; i < 8; i++) {
        int idx = tid + i * 256;
        int row = idx >> 5, kg = idx & 31;
        *(uint4*)(As + row * PALD + kg * 8) =
            *(const uint4*)(g_ctxh + (size_t)(m0 + row) * 256 + kg * 8);
    }
    #pragma unroll
    for (int i = 0; i < 8; i++) {
        int idx = tid + i * 256;
        int row = idx >> 5, kg = idx & 31;
        *(uint4*)(Bs + row * PALD + kg * 8) =
            *(const uint4*)(g_woh + (size_t)(n0blk + row) * 256 + kg * 8);
    }
    __syncthreads();

    uint32_t a_base = sm_u32(As) + (((wm + (lane & 15)) * PALD + (lane >> 4) * 8) << 1);
    uint32_t b_base = sm_u32(Bs) +
        (((wn + ((lane >> 4) << 3) + (lane & 7)) * PALD + ((lane >> 3) & 1) * 8) << 1);

    float c[4][4];
    #pragma unroll
    for (int nj = 0; nj < 4; nj++)
        #pragma unroll
        for (int k = 0; k < 4; k++) c[nj][k] = 0.f;

    #pragma unroll
    for (int kt = 0; kt < 16; kt++) {
        uint32_t a[4];
        LDSM_X4(a, a_base + kt * 32);
        uint32_t bb[2][4];
        #pragma unroll
        for (int p = 0; p < 2; p++)
            LDSM_X4(bb[p], b_base + p * 16 * PALD * 2 + kt * 32);
        #pragma unroll
        for (int nj = 0; nj < 4; nj++)
            MMA16816(c[nj], a, bb[nj >> 1][(nj & 1) * 2], bb[nj >> 1][(nj & 1) * 2 + 1]);
    }

    #pragma unroll
    for (int r = 0; r < 2; r++) {
        int token = m0 + wm + g + r * 8;
        #pragma unroll
        for (int nj = 0; nj < 4; nj++) {
            int col = n0blk + wn + nj * 8 + tg * 2;
            float2 d = *(const float2*)&det[(size_t)token * 256 + col];
            float2 v;
            v.x = c[nj][r * 2 + 0] + b_o[col] + d.x;
            v.y = c[nj][r * 2 + 1] + b_o[col + 1] + d.y;
            *(float2*)&g_x[(size_t)token * 256 + col] = v;
        }
    }
}

// ============================================================
// Pairwise MLP v8: warp owns 16 t-rows x all 128 h; BARRIER-FREE n-loop;
// LN fused in prologue; tracks+w1 smem-resident; xn scaled into A frags.
// ============================================================
#define NPER 8
#define ALDH 264
#define BLDH 264
#define MLP_DYN (128 * ALDH * 2 + 128 * BLDH * 2)   // 135168

__global__ void __launch_bounds__(256, 1)
mlp_mma(const float* __restrict__ ln_g, const float* __restrict__ ln_b,
        const float* __restrict__ b1,
        const float* __restrict__ w2,
        const float* __restrict__ b2,
        float* __restrict__ out)
{
    extern __shared__ __align__(16) char dyn[];
    __half* As = (__half*)dyn;                     // tracks [128][ALDH]
    __half* Bs = (__half*)(dyn + 128 * ALDH * 2);  // w1     [128][BLDH]
    __shared__ float b1s[128], w2s[128];
    __shared__ __half2 xns[NPER][128];

    int b  = blockIdx.z;
    int t0 = blockIdx.x * 128;
    int n0 = blockIdx.y * NPER;
    int tid = threadIdx.x;
    int warp = tid >> 5, lane = tid & 31;
    int wt = warp * 16;          // each warp: 16 t-rows, all 128 h
    int tg = lane & 3, g = lane >> 2;

    if (tid < 128) { b1s[tid] = b1[tid]; w2s[tid] = w2[tid]; }
    float bias2 = b2[0];

    // ---- fused LayerNorm: warp w handles row n0+w ----
    {
        const float* xrow = g_x + ((size_t)(b * ND + n0 + warp)) * 256;
        float4 v0 = *(const float4*)&xrow[lane * 8];
        float4 v1 = *(const float4*)&xrow[lane * 8 + 4];
        float s1 = v0.x + v0.y + v0.z + v0.w + v1.x + v1.y + v1.z + v1.w;
        float s2 = v0.x*v0.x + v0.y*v0.y + v0.z*v0.z + v0.w*v0.w
                 + v1.x*v1.x + v1.y*v1.y + v1.z*v1.z + v1.w*v1.w;
        #pragma unroll
        for (int o = 16; o; o >>= 1) {
            s1 += __shfl_xor_sync(0xffffffffu, s1, o);
            s2 += __shfl_xor_sync(0xffffffffu, s2, o);
        }
        float mu  = s1 * (1.f / 256.f);
        float var = s2 * (1.f / 256.f) - mu * mu;
        float rs  = rsqrtf(var + 1e-5f);
        float4 g0 = *(const float4*)&ln_g[lane * 8];
        float4 g1 = *(const float4*)&ln_g[lane * 8 + 4];
        float4 bb0 = *(const float4*)&ln_b[lane * 8];
        float4 bb1 = *(const float4*)&ln_b[lane * 8 + 4];
        xns[warp][lane * 4 + 0] = __floats2half2_rn(
            (v0.x - mu) * rs * g0.x + bb0.x, (v0.y - mu) * rs * g0.y + bb0.y);
        xns[warp][lane * 4 + 1] = __floats2half2_rn(
            (v0.z - mu) * rs * g0.z + bb0.z, (v0.w - mu) * rs * g0.w + bb0.w);
        xns[warp][lane * 4 + 2] = __floats2half2_rn(
            (v1.x - mu) * rs * g1.x + bb1.x, (v1.y - mu) * rs * g1.y + bb1.y);
        xns[warp][lane * 4 + 3] = __floats2half2_rn(
            (v1.z - mu) * rs * g1.z + bb1.z, (v1.w - mu) * rs * g1.w + bb1.w);
    }

    // ---- stage tracks (A) and w1 (B) once ----
    const __half* trkh = g_trkh + ((size_t)(b * NT + t0)) * 256;
    #pragma unroll
    for (int i = 0; i < 16; i++) {
        int idx = tid + i * 256;
        int row = idx >> 5, kg = idx & 31;
        *(uint4*)(As + row * ALDH + kg * 8) =
            *(const uint4*)(trkh + row * 256 + kg * 8);
    }
    #pragma unroll
    for (int i = 0; i < 16; i++) {
        int idx = tid + i * 256;
        int row = idx >> 5, kg = idx & 31;
        *(uint4*)(Bs + row * BLDH + kg * 8) =
            *(const uint4*)(g_w1h + row * 256 + kg * 8);
    }
    __syncthreads();   // the ONLY block barrier

    uint32_t a_base = sm_u32(As) +
        (((wt + (lane & 15)) * ALDH + (lane >> 4) * 8) << 1);
    uint32_t b_base = sm_u32(Bs) +
        (((((lane >> 4) << 3) + (lane & 7)) * BLDH + ((lane >> 3) & 1) * 8) << 1);

    for (int ni = 0; ni < NPER; ni++) {
        int n = n0 + ni;

        float c[16][4];
        #pragma unroll
        for (int nj = 0; nj < 16; nj++)
            #pragma unroll
            for (int k = 0; k < 4; k++) c[nj][k] = 0.f;

        #pragma unroll
        for (int kk = 0; kk < 16; kk++) {
            uint32_t a[4];
            LDSM_X4(a, a_base + kk * 32);
            __half2 xlo = xns[ni][kk * 8 + tg];
            __half2 xhi = xns[ni][kk * 8 + 4 + tg];
            {
                __half2* ap = (__half2*)a;
                ap[0] = __hmul2(ap[0], xlo);
                ap[1] = __hmul2(ap[1], xlo);
                ap[2] = __hmul2(ap[2], xhi);
                ap[3] = __hmul2(ap[3], xhi);
            }
            #pragma unroll
            for (int p = 0; p < 8; p++) {
                uint32_t bb[4];
                LDSM_X4(bb, b_base + p * 16 * BLDH * 2 + kk * 32);
                MMA16816(c[p * 2],     a, bb[0], bb[1]);
                MMA16816(c[p * 2 + 1], a, bb[2], bb[3]);
            }
        }

        // ---- warp-local epilogue (no smem, no barrier) ----
        float s0 = 0.f, s1 = 0.f;
        #pragma unroll
        for (int nj = 0; nj < 16; nj++) {
            int col0 = nj * 8 + tg * 2;
            float bb0 = b1s[col0], ww0 = w2s[col0];
            float bb1 = b1s[col0 + 1], ww1 = w2s[col0 + 1];
            s0 += fmaxf(c[nj][0] + bb0, 0.f) * ww0
                + fmaxf(c[nj][1] + bb1, 0.f) * ww1;
            s1 += fmaxf(c[nj][2] + bb0, 0.f) * ww0
                + fmaxf(c[nj][3] + bb1, 0.f) * ww1;
        }
        s0 += __shfl_xor_sync(0xffffffffu, s0, 1);
        s0 += __shfl_xor_sync(0xffffffffu, s0, 2);
        s1 += __shfl_xor_sync(0xffffffffu, s1, 1);
        s1 += __shfl_xor_sync(0xffffffffu, s1, 2);
        if (tg == 0) {
            size_t base = ((size_t)(b * ND + n)) * NT + t0;
            out[base + wt + g]     = 1.f / (1.f + __expf(-(s0 + bias2)));
            out[base + wt + g + 8] = 1.f / (1.f + __expf(-(s1 + bias2)));
        }
    }
}

// ============================================================
extern "C" void kernel_launch(void* const* d_in, const int* in_sizes, int n_in,
                              void* d_out, int out_size)
{
    const float* det  = (const float*)d_in[0];
    const float* trk  = (const float*)d_in[1];
    const float* w_q  = (const float*)d_in[2];
    const float* b_q  = (const float*)d_in[3];
    const float* w_k  = (const float*)d_in[4];
    const float* b_k  = (const float*)d_in[5];
    const float* w_v  = (const float*)d_in[6];
    const float* b_v  = (const float*)d_in[7];
    const float* w_o  = (const float*)d_in[8];
    const float* b_o  = (const float*)d_in[9];
    const float* ln_g = (const float*)d_in[10];
    const float* ln_b = (const float*)d_in[11];
    const float* w1   = (const float*)d_in[12];
    const float* b1   = (const float*)d_in[13];
    const float* w2   = (const float*)d_in[14];
    const float* b2   = (const float*)d_in[15];
    float* out = (float*)d_out;

    cudaFuncSetAttribute(mlp_mma,
                         cudaFuncAttributeMaxDynamicSharedMemorySize, MLP_DYN);
    cudaFuncSetAttribute(proj_gemm,
                         cudaFuncAttributeMaxDynamicSharedMemorySize, PROJ_SMEM);
    cudaFuncSetAttribute(gemm_o_tc,
                         cudaFuncAttributeMaxDynamicSharedMemorySize, GO_SMEM);

    prep_half<<<2048, 256>>>(det, trk, w_q, w_k, w_v, w_o, w1);
    proj_gemm<<<dim3(32, 2, 3), 256, PROJ_SMEM>>>(b_q, b_k, b_v);
    attn_tc<<<dim3(8, NH, BB), 128>>>();
    gemm_o_tc<<<dim3(32, 4), 256, GO_SMEM>>>(b_o, det);
    mlp_mma<<<dim3(4, ND / NPER, BB), 256, MLP_DYN>>>(ln_g, ln_b, b1, w2, b2, out);
}

// round 16
// speedup vs baseline: 1.0734x; 1.0734x over previous
#include <cuda_runtime.h>
#include <cuda_fp16.h>
#include <math.h>
#include <stdint.h>

#define BB 4
#define ND 512
#define NT 512
#define DM 256
#define NH 8
#define DK 32

// ---- scratch (static device globals; no runtime allocation) ----
__device__ __half g_deth[BB*ND*DM];       // detections fp16
__device__ __half g_trkh[BB*NT*DM];       // tracks fp16
__device__ __half g_wqh[DM*DM], g_wkh[DM*DM], g_wvh[DM*DM], g_woh[DM*DM];
__device__ __half g_w1h[128*DM];
__device__ __half g_Qh[BB*NH*ND*DK];      // [bh][q][dk]
__device__ __half g_Kh[BB*NH*NT*DK];      // [bh][t][dk]
__device__ __half g_Vht[BB*NH*DK*NT];     // [bh][dk][t]  (transposed)
__device__ __half g_ctxh[BB*ND*DM];       // attention output fp16 [token][256]
__device__ float g_x[BB*ND*DM];           // residual x = det + attended (fp32)

static __device__ __forceinline__ uint32_t sm_u32(const void* p) {
    uint32_t a;
    asm("{ .reg .u64 t; cvta.to.shared.u64 t, %1; cvt.u32.u64 %0, t; }"
        : "=r"(a) : "l"(p));
    return a;
}
static __device__ __forceinline__ uint32_t f2h2(float a, float b) {
    __half2 h = __floats2half2_rn(a, b);
    return *reinterpret_cast<uint32_t*>(&h);
}

#define LDSM_X4(r, addr) \
    asm volatile("ldmatrix.sync.aligned.m8n8.x4.shared.b16 {%0,%1,%2,%3}, [%4];" \
        : "=r"((r)[0]), "=r"((r)[1]), "=r"((r)[2]), "=r"((r)[3]) : "r"(addr))
#define MMA16816(c, a, b0, b1) \
    asm volatile("mma.sync.aligned.m16n8k16.row.col.f32.f16.f16.f32 " \
        "{%0,%1,%2,%3}, {%4,%5,%6,%7}, {%8,%9}, {%0,%1,%2,%3};" \
        : "+f"((c)[0]), "+f"((c)[1]), "+f"((c)[2]), "+f"((c)[3]) \
        : "r"((a)[0]), "r"((a)[1]), "r"((a)[2]), "r"((a)[3]), "r"(b0), "r"(b1))

// ============================================================
// prep: fp32 -> fp16 copies (everything converted exactly once)
// ============================================================
__global__ void prep_half(const float* __restrict__ det,
                          const float* __restrict__ trk,
                          const float* __restrict__ w_q, const float* __restrict__ w_k,
                          const float* __restrict__ w_v, const float* __restrict__ w_o,
                          const float* __restrict__ w1)
{
    int idx = blockIdx.x * 256 + threadIdx.x;   // 0 .. 524287
    g_deth[idx] = __float2half_rn(det[idx]);
    g_trkh[idx] = __float2half_rn(trk[idx]);
    if (idx < DM * DM) {
        g_wqh[idx] = __float2half_rn(w_q[idx]);
        g_wkh[idx] = __float2half_rn(w_k[idx]);
        g_wvh[idx] = __float2half_rn(w_v[idx]);
        g_woh[idx] = __float2half_rn(w_o[idx]);
    }
    if (idx < 128 * DM) g_w1h[idx] = __float2half_rn(w1[idx]);
}

// ============================================================
// Projection GEMM (fp16 mma, pre-converted inputs):
//   z = 0: Q -> g_Qh;  z = 1: K -> g_Kh;  z = 2: V -> g_Vht via smem transpose
// ============================================================
#define PALD 264
#define TLD 72
#define PROJ_SMEM ((64 * PALD + 128 * PALD) * 2)   // 101376

__global__ void __launch_bounds__(256)
proj_gemm(const float* __restrict__ b_q, const float* __restrict__ b_k,
          const float* __restrict__ b_v)
{
    int z = blockIdx.z;
    const __half* X = (z == 0) ? g_deth : g_trkh;
    const __half* W = (z == 0) ? g_wqh : (z == 1) ? g_wkh : g_wvh;
    const float* bias = (z == 0) ? b_q : (z == 1) ? b_k : b_v;

    extern __shared__ __align__(16) char dyn[];
    __half* As = (__half*)dyn;                      // [64][PALD]
    __half* Bs = (__half*)(dyn + 64 * PALD * 2);    // [128][PALD]
    __half* T  = (__half*)dyn;                      // overlay: [128 col][TLD]

    int tid = threadIdx.x;
    int warp = tid >> 5, lane = tid & 31;
    int m0 = blockIdx.x * 64, n0blk = blockIdx.y * 128;
    int wm = (warp & 3) * 16, wn = (warp >> 2) * 64;
    int tg = lane & 3, g = lane >> 2;

    #pragma unroll
    for (int i = 0; i < 8; i++) {
        int idx = tid + i * 256;
        int row = idx >> 5, kg = idx & 31;
        *(uint4*)(As + row * PALD + kg * 8) =
            *(const uint4*)(X + (size_t)(m0 + row) * 256 + kg * 8);
    }
    #pragma unroll
    for (int i = 0; i < 16; i++) {
        int idx = tid + i * 256;
        int row = idx >> 5, kg = idx & 31;
        *(uint4*)(Bs + row * PALD + kg * 8) =
            *(const uint4*)(W + (size_t)(n0blk + row) * 256 + kg * 8);
    }
    __syncthreads();

    uint32_t a_base = sm_u32(As) + (((wm + (lane & 15)) * PALD + (lane >> 4) * 8) << 1);
    uint32_t b_base = sm_u32(Bs) +
        (((wn + ((lane >> 4) << 3) + (lane & 7)) * PALD + ((lane >> 3) & 1) * 8) << 1);

    float c[8][4];
    #pragma unroll
    for (int nj = 0; nj < 8; nj++)
        #pragma unroll
        for (int k = 0; k < 4; k++) c[nj][k] = 0.f;

    #pragma unroll
    for (int kt = 0; kt < 16; kt++) {
        uint32_t a[4];
        LDSM_X4(a, a_base + kt * 32);
        uint32_t bb[4][4];
        #pragma unroll
        for (int p = 0; p < 4; p++)
            LDSM_X4(bb[p], b_base + p * 16 * PALD * 2 + kt * 32);
        #pragma unroll
        for (int nj = 0; nj < 8; nj++)
            MMA16816(c[nj], a, bb[nj >> 1][(nj & 1) * 2], bb[nj >> 1][(nj & 1) * 2 + 1]);
    }

    if (z != 2) {
        #pragma unroll
        for (int r = 0; r < 2; r++) {
            int token = m0 + wm + g + r * 8;
            int b = token >> 9, tk = token & 511;
            #pragma unroll
            for (int nj = 0; nj < 8; nj++) {
                int col = n0blk + wn + nj * 8 + tg * 2;
                int h = col >> 5, dk = col & 31;
                float v0 = c[nj][r * 2 + 0] + bias[col];
                float v1 = c[nj][r * 2 + 1] + bias[col + 1];
                int bh = b * NH + h;
                if (z == 0) {
                    *(__half2*)&g_Qh[((size_t)(bh * ND + tk)) * DK + dk] =
                        __floats2half2_rn(v0, v1);
                } else {
                    *(__half2*)&g_Kh[((size_t)(bh * NT + tk)) * DK + dk] =
                        __floats2half2_rn(v0, v1);
                }
            }
        }
    } else {
        __syncthreads();
        #pragma unroll
        for (int r = 0; r < 2; r++) {
            int tok = wm + g + r * 8;
            #pragma unroll
            for (int nj = 0; nj < 8; nj++) {
                int col = wn + nj * 8 + tg * 2;
                T[col * TLD + tok]       =
                    __float2half_rn(c[nj][r * 2 + 0] + b_v[n0blk + col]);
                T[(col + 1) * TLD + tok] =
                    __float2half_rn(c[nj][r * 2 + 1] + b_v[n0blk + col + 1]);
            }
        }
        __syncthreads();
        int b = m0 >> 9, tk0 = m0 & 511;
        #pragma unroll
        for (int i = 0; i < 4; i++) {
            int idx = tid + i * 256;
            int cloc = idx >> 3, part = idx & 7;
            int gcol = n0blk + cloc;
            int h = gcol >> 5, dk = gcol & 31;
            *(uint4*)&g_Vht[((size_t)((b * NH + h) * DK + dk)) * NT + tk0 + part * 8] =
                *(const uint4*)(T + cloc * TLD + part * 8);
        }
    }
}

// ============================================================
// Flash attention v4: double-buffered K/V smem + register prefetch,
// ONE barrier per chunk. q-tile 64, 128 thr, no-max softmax.
// ============================================================
#define QLD 40
#define VLD 72
#define KBUF (64 * QLD)
#define VBUF (32 * VLD)

__global__ void __launch_bounds__(128) attn_tc()
{
    __shared__ __half Qs[64 * QLD];
    __shared__ __half Ks[2][KBUF];
    __shared__ __half Vt[2][VBUF];

    int bh = blockIdx.z * NH + blockIdx.y;
    int q0 = blockIdx.x * 64;
    int h  = blockIdx.y;
    int tid = threadIdx.x;
    int warp = tid >> 5, lane = tid & 31;
    int tg = lane & 3, g = lane >> 2;

    int krow0 = tid >> 2,         kpart0 = tid & 3;
    int krow1 = (tid + 128) >> 2, kpart1 = tid & 3;
    int vrow0 = tid >> 3,         vpart0 = tid & 7;
    int vrow1 = (tid + 128) >> 3, vpart1 = tid & 7;

    #pragma unroll
    for (int i = 0; i < 2; i++) {
        int idx = tid + i * 128;
        int row = idx >> 2, part = idx & 3;
        *(uint4*)(Qs + row * QLD + part * 8) =
            *(const uint4*)(g_Qh + ((size_t)(bh * ND + q0 + row)) * DK + part * 8);
    }
    *(uint4*)(Ks[0] + krow0 * QLD + kpart0 * 8) =
        *(const uint4*)(g_Kh + ((size_t)(bh * NT + krow0)) * DK + kpart0 * 8);
    *(uint4*)(Ks[0] + krow1 * QLD + kpart1 * 8) =
        *(const uint4*)(g_Kh + ((size_t)(bh * NT + krow1)) * DK + kpart1 * 8);
    *(uint4*)(Vt[0] + vrow0 * VLD + vpart0 * 8) =
        *(const uint4*)(g_Vht + ((size_t)(bh * DK + vrow0)) * NT + vpart0 * 8);
    *(uint4*)(Vt[0] + vrow1 * VLD + vpart1 * 8) =
        *(const uint4*)(g_Vht + ((size_t)(bh * DK + vrow1)) * NT + vpart1 * 8);
    __syncthreads();

    uint32_t aq_base = sm_u32(Qs) +
        (((warp * 16 + (lane & 15)) * QLD + (lane >> 4) * 8) << 1);
    uint32_t bk0 = sm_u32(Ks) +
        (((((lane >> 4) << 3) + (lane & 7)) * QLD + ((lane >> 3) & 1) * 8) << 1);
    uint32_t bv0 = sm_u32(Vt) +
        (((((lane >> 4) << 3) + (lane & 7)) * VLD + ((lane >> 3) & 1) * 8) << 1);

    uint32_t aQ[2][4];
    LDSM_X4(aQ[0], aq_base);
    LDSM_X4(aQ[1], aq_base + 32);

    const float scale = 0.17677669529663689f;
    float l0 = 0.f, l1 = 0.f;
    float c2[4][4];
    #pragma unroll
    for (int nt = 0; nt < 4; nt++)
        #pragma unroll
        for (int k = 0; k < 4; k++) c2[nt][k] = 0.f;

    for (int ch = 0; ch < 8; ch++) {
        uint4 kpre0, kpre1, vpre0, vpre1;
        if (ch < 7) {
            int t0 = (ch + 1) * 64;
            kpre0 = *(const uint4*)(g_Kh + ((size_t)(bh * NT + t0 + krow0)) * DK + kpart0 * 8);
            kpre1 = *(const uint4*)(g_Kh + ((size_t)(bh * NT + t0 + krow1)) * DK + kpart1 * 8);
            vpre0 = *(const uint4*)(g_Vht + ((size_t)(bh * DK + vrow0)) * NT + t0 + vpart0 * 8);
            vpre1 = *(const uint4*)(g_Vht + ((size_t)(bh * DK + vrow1)) * NT + t0 + vpart1 * 8);
        }

        int cur = ch & 1;
        uint32_t bk_base = bk0 + cur * (KBUF * 2);
        uint32_t bv_base = bv0 + cur * (VBUF * 2);

        float c[8][4];
        #pragma unroll
        for (int nj = 0; nj < 8; nj++)
            #pragma unroll
            for (int k = 0; k < 4; k++) c[nj][k] = 0.f;
        #pragma unroll
        for (int kt = 0; kt < 2; kt++) {
            uint32_t bb[4][4];
            #pragma unroll
            for (int p = 0; p < 4; p++)
                LDSM_X4(bb[p], bk_base + p * 16 * QLD * 2 + kt * 32);
            #pragma unroll
            for (int nj = 0; nj < 8; nj++)
                MMA16816(c[nj], aQ[kt],
                         bb[nj >> 1][(nj & 1) * 2], bb[nj >> 1][(nj & 1) * 2 + 1]);
        }

        uint32_t af[4][4];
        #pragma unroll
        for (int nj = 0; nj < 8; nj++) {
            float p0 = __expf(fminf(c[nj][0] * scale, 11.f));
            float p1 = __expf(fminf(c[nj][1] * scale, 11.f));
            float p2 = __expf(fminf(c[nj][2] * scale, 11.f));
            float p3 = __expf(fminf(c[nj][3] * scale, 11.f));
            l0 += p0 + p1; l1 += p2 + p3;
            int kt = nj >> 1, half = (nj & 1) * 2;
            af[kt][half]     = f2h2(p0, p1);
            af[kt][half + 1] = f2h2(p2, p3);
        }

        #pragma unroll
        for (int kt = 0; kt < 4; kt++) {
            uint32_t bb[2][4];
            #pragma unroll
            for (int p = 0; p < 2; p++)
                LDSM_X4(bb[p], bv_base + p * 16 * VLD * 2 + kt * 32);
            #pragma unroll
            for (int nt = 0; nt < 4; nt++)
                MMA16816(c2[nt], af[kt],
                         bb[nt >> 1][(nt & 1) * 2], bb[nt >> 1][(nt & 1) * 2 + 1]);
        }

        if (ch < 7) {
            int nxt = cur ^ 1;
            *(uint4*)(Ks[nxt] + krow0 * QLD + kpart0 * 8) = kpre0;
            *(uint4*)(Ks[nxt] + krow1 * QLD + kpart1 * 8) = kpre1;
            *(uint4*)(Vt[nxt] + vrow0 * VLD + vpart0 * 8) = vpre0;
            *(uint4*)(Vt[nxt] + vrow1 * VLD + vpart1 * 8) = vpre1;
            __syncthreads();
        }
    }

    l0 += __shfl_xor_sync(0xffffffffu, l0, 1);
    l0 += __shfl_xor_sync(0xffffffffu, l0, 2);
    l1 += __shfl_xor_sync(0xffffffffu, l1, 1);
    l1 += __shfl_xor_sync(0xffffffffu, l1, 2);

    float inv0 = 1.f / l0, inv1 = 1.f / l1;
    int token = q0 + warp * 16 + g;
    #pragma unroll
    for (int nt = 0; nt < 4; nt++) {
        int col = h * DK + nt * 8 + tg * 2;
        size_t base_b = (size_t)(blockIdx.z * ND);
        *(__half2*)&g_ctxh[(base_b + token) * DM + col] =
            __floats2half2_rn(c2[nt][0] * inv0, c2[nt][1] * inv0);
        *(__half2*)&g_ctxh[(base_b + token + 8) * DM + col] =
            __floats2half2_rn(c2[nt][2] * inv1, c2[nt][3] * inv1);
    }
}

// ============================================================
// output projection + residual (64x64 tiles, 128 blocks):
//   x = ctxh @ w_o^T + b_o + det  (fp32)
// ============================================================
#define GO_SMEM ((64 * PALD + 64 * PALD) * 2)   // 67584

__global__ void __launch_bounds__(256)
gemm_o_tc(const float* __restrict__ b_o, const float* __restrict__ det)
{
    extern __shared__ __align__(16) char dyn[];
    __half* As = (__half*)dyn;                   // [64][PALD]
    __half* Bs = (__half*)(dyn + 64 * PALD * 2); // [64][PALD]

    int tid = threadIdx.x;
    int warp = tid >> 5, lane = tid & 31;
    int m0 = blockIdx.x * 64, n0blk = blockIdx.y * 64;
    int wm = (warp & 3) * 16, wn = (warp >> 2) * 32;
    int tg = lane & 3, g = lane >> 2;

    #pragma unroll
    for (int i = 0; i < 8; i++) {
        int idx = tid + i * 256;
        int row = idx >> 5, kg = idx & 31;
        *(uint4*)(As + row * PALD + kg * 8) =
            *(const uint4*)(g_ctxh + (size_t)(m0 + row) * 256 + kg * 8);
    }
    #pragma unroll
    for (int i = 0; i < 8; i++) {
        int idx = tid + i * 256;
        int row = idx >> 5, kg = idx & 31;
        *(uint4*)(Bs + row * PALD + kg * 8) =
            *(const uint4*)(g_woh + (size_t)(n0blk + row) * 256 + kg * 8);
    }
    __syncthreads();

    uint32_t a_base = sm_u32(As) + (((wm + (lane & 15)) * PALD + (lane >> 4) * 8) << 1);
    uint32_t b_base = sm_u32(Bs) +
        (((wn + ((lane >> 4) << 3) + (lane & 7)) * PALD + ((lane >> 3) & 1) * 8) << 1);

    float c[4][4];
    #pragma unroll
    for (int nj = 0; nj < 4; nj++)
        #pragma unroll
        for (int k = 0; k < 4; k++) c[nj][k] = 0.f;

    #pragma unroll
    for (int kt = 0; kt < 16; kt++) {
        uint32_t a[4];
        LDSM_X4(a, a_base + kt * 32);
        uint32_t bb[2][4];
        #pragma unroll
        for (int p = 0; p < 2; p++)
            LDSM_X4(bb[p], b_base + p * 16 * PALD * 2 + kt * 32);
        #pragma unroll
        for (int nj = 0; nj < 4; nj++)
            MMA16816(c[nj], a, bb[nj >> 1][(nj & 1) * 2], bb[nj >> 1][(nj & 1) * 2 + 1]);
    }

    #pragma unroll
    for (int r = 0; r < 2; r++) {
        int token = m0 + wm + g + r * 8;
        #pragma unroll
        for (int nj = 0; nj < 4; nj++) {
            int col = n0blk + wn + nj * 8 + tg * 2;
            float2 d = *(const float2*)&det[(size_t)token * 256 + col];
            float2 v;
            v.x = c[nj][r * 2 + 0] + b_o[col] + d.x;
            v.y = c[nj][r * 2 + 1] + b_o[col + 1] + d.y;
            *(float2*)&g_x[(size_t)token * 256 + col] = v;
        }
    }
}

// ============================================================
// Pairwise MLP v7 (round-14 measured-best): LN fused in prologue,
// tracks+w1 smem-resident, xn scaled into A fragments, f32 acc,
// 4t x 2h warp tiling with psum epilogue.
// ============================================================
#define NPER 8
#define ALDH 264
#define BLDH 264
#define MLP_DYN (128 * ALDH * 2 + 128 * BLDH * 2)   // 135168

__global__ void __launch_bounds__(256, 1)
mlp_mma(const float* __restrict__ ln_g, const float* __restrict__ ln_b,
        const float* __restrict__ b1,
        const float* __restrict__ w2,
        const float* __restrict__ b2,
        float* __restrict__ out)
{
    extern __shared__ __align__(16) char dyn[];
    __half* As = (__half*)dyn;                     // tracks [128][ALDH]
    __half* Bs = (__half*)(dyn + 128 * ALDH * 2);  // w1     [128][BLDH]
    __shared__ float b1s[128], w2s[128];
    __shared__ float psum[2][128];
    __shared__ __half2 xns[NPER][128];

    int b  = blockIdx.z;
    int t0 = blockIdx.x * 128;
    int n0 = blockIdx.y * NPER;
    int tid = threadIdx.x;
    int warp = tid >> 5, lane = tid & 31;
    int wt = (warp & 3) * 32;
    int wh = (warp >> 2) * 64;
    int tg = lane & 3, g = lane >> 2;

    if (tid < 128) { b1s[tid] = b1[tid]; w2s[tid] = w2[tid]; }
    float bias2 = b2[0];

    // ---- fused LayerNorm: warp w handles row n0+w ----
    {
        const float* xrow = g_x + ((size_t)(b * ND + n0 + warp)) * 256;
        float4 v0 = *(const float4*)&xrow[lane * 8];
        float4 v1 = *(const float4*)&xrow[lane * 8 + 4];
        float s1 = v0.x + v0.y + v0.z + v0.w + v1.x + v1.y + v1.z + v1.w;
        float s2 = v0.x*v0.x + v0.y*v0.y + v0.z*v0.z + v0.w*v0.w
                 + v1.x*v1.x + v1.y*v1.y + v1.z*v1.z + v1.w*v1.w;
        #pragma unroll
        for (int o = 16; o; o >>= 1) {
            s1 += __shfl_xor_sync(0xffffffffu, s1, o);
            s2 += __shfl_xor_sync(0xffffffffu, s2, o);
        }
        float mu  = s1 * (1.f / 256.f);
        float var = s2 * (1.f / 256.f) - mu * mu;
        float rs  = rsqrtf(var + 1e-5f);
        float4 g0 = *(const float4*)&ln_g[lane * 8];
        float4 g1 = *(const float4*)&ln_g[lane * 8 + 4];
        float4 bb0 = *(const float4*)&ln_b[lane * 8];
        float4 bb1 = *(const float4*)&ln_b[lane * 8 + 4];
        xns[warp][lane * 4 + 0] = __floats2half2_rn(
            (v0.x - mu) * rs * g0.x + bb0.x, (v0.y - mu) * rs * g0.y + bb0.y);
        xns[warp][lane * 4 + 1] = __floats2half2_rn(
            (v0.z - mu) * rs * g0.z + bb0.z, (v0.w - mu) * rs * g0.w + bb0.w);
        xns[warp][lane * 4 + 2] = __floats2half2_rn(
            (v1.x - mu) * rs * g1.x + bb1.x, (v1.y - mu) * rs * g1.y + bb1.y);
        xns[warp][lane * 4 + 3] = __floats2half2_rn(
            (v1.z - mu) * rs * g1.z + bb1.z, (v1.w - mu) * rs * g1.w + bb1.w);
    }

    // ---- stage tracks (A) and w1 (B) once ----
    const __half* trkh = g_trkh + ((size_t)(b * NT + t0)) * 256;
    #pragma unroll
    for (int i = 0; i < 16; i++) {
        int idx = tid + i * 256;
        int row = idx >> 5, kg = idx & 31;
        *(uint4*)(As + row * ALDH + kg * 8) =
            *(const uint4*)(trkh + row * 256 + kg * 8);
    }
    #pragma unroll
    for (int i = 0; i < 16; i++) {
        int idx = tid + i * 256;
        int row = idx >> 5, kg = idx & 31;
        *(uint4*)(Bs + row * BLDH + kg * 8) =
            *(const uint4*)(g_w1h + row * 256 + kg * 8);
    }
    __syncthreads();

    uint32_t a_base = sm_u32(As) +
        (((wt + (lane & 15)) * ALDH + (lane >> 4) * 8) << 1);
    uint32_t b_base = sm_u32(Bs) +
        (((wh + ((lane >> 4) << 3) + (lane & 7)) * BLDH + ((lane >> 3) & 1) * 8) << 1);

    for (int ni = 0; ni < NPER; ni++) {
        int n = n0 + ni;
        int par = ni & 1;

        float c[2][8][4];
        #pragma unroll
        for (int mi = 0; mi < 2; mi++)
            #pragma unroll
            for (int nj = 0; nj < 8; nj++)
                #pragma unroll
                for (int k = 0; k < 4; k++) c[mi][nj][k] = 0.f;

        #pragma unroll
        for (int kk = 0; kk < 16; kk++) {
            uint32_t a[2][4];
            LDSM_X4(a[0], a_base + kk * 32);
            LDSM_X4(a[1], a_base + 16 * ALDH * 2 + kk * 32);
            __half2 xlo = xns[ni][kk * 8 + tg];
            __half2 xhi = xns[ni][kk * 8 + 4 + tg];
            #pragma unroll
            for (int mi = 0; mi < 2; mi++) {
                __half2* ap = (__half2*)a[mi];
                ap[0] = __hmul2(ap[0], xlo);
                ap[1] = __hmul2(ap[1], xlo);
                ap[2] = __hmul2(ap[2], xhi);
                ap[3] = __hmul2(ap[3], xhi);
            }
            uint32_t bb[4][4];
            #pragma unroll
            for (int p = 0; p < 4; p++)
                LDSM_X4(bb[p], b_base + p * 16 * BLDH * 2 + kk * 32);
            #pragma unroll
            for (int mi = 0; mi < 2; mi++)
                #pragma unroll
                for (int nj = 0; nj < 8; nj++)
                    MMA16816(c[mi][nj], a[mi],
                             bb[nj >> 1][(nj & 1) * 2], bb[nj >> 1][(nj & 1) * 2 + 1]);
        }

        float sreg[2][2];
        #pragma unroll
        for (int mi = 0; mi < 2; mi++) {
            float s0 = 0.f, s1 = 0.f;
            #pragma unroll
            for (int nj = 0; nj < 8; nj++) {
                int col0 = wh + nj * 8 + tg * 2;
                float bb0 = b1s[col0], ww0 = w2s[col0];
                float bb1 = b1s[col0 + 1], ww1 = w2s[col0 + 1];
                s0 += fmaxf(c[mi][nj][0] + bb0, 0.f) * ww0
                    + fmaxf(c[mi][nj][1] + bb1, 0.f) * ww1;
                s1 += fmaxf(c[mi][nj][2] + bb0, 0.f) * ww0
                    + fmaxf(c[mi][nj][3] + bb1, 0.f) * ww1;
            }
            s0 += __shfl_xor_sync(0xffffffffu, s0, 1);
            s0 += __shfl_xor_sync(0xffffffffu, s0, 2);
            s1 += __shfl_xor_sync(0xffffffffu, s1, 1);
            s1 += __shfl_xor_sync(0xffffffffu, s1, 2);
            sreg[mi][0] = s0; sreg[mi][1] = s1;
            if (warp >= 4 && tg == 0) {
                psum[par][wt + mi * 16 + g]     = s0;
                psum[par][wt + mi * 16 + g + 8] = s1;
            }
        }
        __syncthreads();
        if (warp < 4 && tg == 0) {
            #pragma unroll
            for (int mi = 0; mi < 2; mi++) {
                int t = wt + mi * 16 + g;
                float l0 = sreg[mi][0] + psum[par][t]     + bias2;
                float l1 = sreg[mi][1] + psum[par][t + 8] + bias2;
                size_t base = ((size_t)(b * ND + n)) * NT + t0;
                out[base + t]     = 1.f / (1.f + __expf(-l0));
                out[base + t + 8] = 1.f / (1.f + __expf(-l1));
            }
        }
    }
}

// ============================================================
extern "C" void kernel_launch(void* const* d_in, const int* in_sizes, int n_in,
                              void* d_out, int out_size)
{
    const float* det  = (const float*)d_in[0];
    const float* trk  = (const float*)d_in[1];
    const float* w_q  = (const float*)d_in[2];
    const float* b_q  = (const float*)d_in[3];
    const float* w_k  = (const float*)d_in[4];
    const float* b_k  = (const float*)d_in[5];
    const float* w_v  = (const float*)d_in[6];
    const float* b_v  = (const float*)d_in[7];
    const float* w_o  = (const float*)d_in[8];
    const float* b_o  = (const float*)d_in[9];
    const float* ln_g = (const float*)d_in[10];
    const float* ln_b = (const float*)d_in[11];
    const float* w1   = (const float*)d_in[12];
    const float* b1   = (const float*)d_in[13];
    const float* w2   = (const float*)d_in[14];
    const float* b2   = (const float*)d_in[15];
    float* out = (float*)d_out;

    cudaFuncSetAttribute(mlp_mma,
                         cudaFuncAttributeMaxDynamicSharedMemorySize, MLP_DYN);
    cudaFuncSetAttribute(proj_gemm,
                         cudaFuncAttributeMaxDynamicSharedMemorySize, PROJ_SMEM);
    cudaFuncSetAttribute(gemm_o_tc,
                         cudaFuncAttributeMaxDynamicSharedMemorySize, GO_SMEM);

    prep_half<<<2048, 256>>>(det, trk, w_q, w_k, w_v, w_o, w1);
    proj_gemm<<<dim3(32, 2, 3), 256, PROJ_SMEM>>>(b_q, b_k, b_v);
    attn_tc<<<dim3(8, NH, BB), 128>>>();
    gemm_o_tc<<<dim3(32, 4), 256, GO_SMEM>>>(b_o, det);
    mlp_mma<<<dim3(4, ND / NPER, BB), 256, MLP_DYN>>>(ln_g, ln_b, b1, w2, b2, out);
}